// round 14
// baseline (speedup 1.0000x reference)
#include <cuda_runtime.h>
#include <cuda_fp16.h>
#include <math.h>
#include <cstdint>

#define BB 64
#define DIM 640
#define MK 100
#define TT 128
#define NT 5            // DIM / TT
#define NPAIR 15        // upper tile pairs
#define TRI 205120      // 640*641/2
#define EPSV 1e-5f
#define SPAD 104        // even stride; fp16 LDS.64 frag loads conflict-free (8g+2t)
#define TSZ (TT * SPAD)
#define NROWS (BB * DIM)

// ---- scratch (static device arrays: allocation-free) ----
__device__ float g_sp[NT][BB][DIM];   // row-sum slots (exactly-once writes)
__device__ float g_d[NROWS];          // squared norms
__device__ float g_sb[NROWS];         // per-batch row sums, pre-scaled by 1/dim
__device__ float g_gm[BB];            // per-batch grand mean

// ---------------------------------------------------------------------------
__device__ __forceinline__ uint32_t f2tf32(float v) {
    uint32_t r;
    asm("cvt.rna.tf32.f32 %0, %1;" : "=r"(r) : "f"(v));
    return r;
}
// fp16 m16n8k16 MMA, f32 accumulate
__device__ __forceinline__ void mma16(float* c, const uint32_t* a, const uint32_t* b) {
    asm volatile(
        "mma.sync.aligned.m16n8k16.row.col.f32.f16.f16.f32 "
        "{%0,%1,%2,%3}, {%4,%5,%6,%7}, {%8,%9}, {%0,%1,%2,%3};"
        : "+f"(c[0]), "+f"(c[1]), "+f"(c[2]), "+f"(c[3])
        : "r"(a[0]), "r"(a[1]), "r"(a[2]), "r"(a[3]), "r"(b[0]), "r"(b[1]));
}
// tf32 m16n8k8 MMA (final k-step 96..103)
__device__ __forceinline__ void mma8(float* c, const uint32_t* a, const uint32_t* b) {
    asm volatile(
        "mma.sync.aligned.m16n8k8.row.col.f32.tf32.tf32.f32 "
        "{%0,%1,%2,%3}, {%4,%5,%6,%7}, {%8,%9}, {%0,%1,%2,%3};"
        : "+f"(c[0]), "+f"(c[1]), "+f"(c[2]), "+f"(c[3])
        : "r"(a[0]), "r"(a[1]), "r"(a[2]), "r"(a[3]), "r"(b[0]), "r"(b[1]));
}
// split a float2 (k even, k odd) into fp16 hi pair + fp16 lo pair
__device__ __forceinline__ void split_h2(float2 p, uint32_t& hi, uint32_t& lo) {
    __half2 h = __floats2half2_rn(p.x, p.y);                 // lo half = p.x (even k)
    hi = *reinterpret_cast<uint32_t*>(&h);
    __half2 l = __floats2half2_rn(p.x - __low2float(h), p.y - __high2float(h));
    lo = *reinterpret_cast<uint32_t*>(&l);
}

// ---------------------------------------------------------------------------
// Norms: one warp per x-row (coalesced), split over batch thirds
// ---------------------------------------------------------------------------
__global__ void norm_kernel(const float* __restrict__ x, int row0, int nrows) {
    int w = (blockIdx.x * 256 + threadIdx.x) >> 5;
    int lane = threadIdx.x & 31;
    if (w >= nrows) return;
    const float* xr = x + (size_t)(row0 + w) * MK;
    float s = 0.f;
#pragma unroll
    for (int k = lane; k < MK; k += 32) { float v = xr[k]; s = fmaf(v, v, s); }
#pragma unroll
    for (int o = 16; o >= 1; o >>= 1) s += __shfl_xor_sync(0xffffffffu, s, o);
    if (lane == 0) g_d[row0 + w] = s;
}

// ---------------------------------------------------------------------------
// Gram: hybrid fp16-split (k 0..95, m16n8k16) + tf32-split (k 96..103, m16n8k8)
// 256 threads, 64x32 warp tiles, 2 CTAs/SM. Triu-direct store.
// ---------------------------------------------------------------------------
__global__ __launch_bounds__(256, 2)
void gram_dcov_kernel(const float* __restrict__ x, const float* __restrict__ t,
                      float* __restrict__ out) {
    int p = blockIdx.x, b = blockIdx.y;
    int ti = 0, rem = p;
    while (rem >= NT - ti) { rem -= NT - ti; ti++; }
    int tj = ti + rem;
    int i0 = ti * TT, j0 = tj * TT;
    bool diag = (ti == tj);

    extern __shared__ float sm[];
    float* A = sm;
    float* B = A + TSZ;

    __shared__ float di_s[TT], dj_s[TT], rs_s[TT], cs_s[TT];

    int tid = threadIdx.x;
    if (tid < TT) { rs_s[tid] = 0.f; cs_s[tid] = 0.f; }

    const float* xb = x + (size_t)b * DIM * MK;

    // ---- stage raw fp32 tiles (straight layout, zeros at k 100..103) ----
    {
        const float* srcA = xb + (size_t)i0 * MK;
        for (int idx = tid; idx < TT * MK; idx += 256) {
            int r = idx / MK, m = idx - r * MK;
            A[r * SPAD + m] = srcA[idx];
        }
        for (int idx = tid; idx < TT * 4; idx += 256)
            A[(idx >> 2) * SPAD + MK + (idx & 3)] = 0.f;
        if (!diag) {
            const float* srcB = xb + (size_t)j0 * MK;
            for (int idx = tid; idx < TT * MK; idx += 256) {
                int r = idx / MK, m = idx - r * MK;
                B[r * SPAD + m] = srcB[idx];
            }
            for (int idx = tid; idx < TT * 4; idx += 256)
                B[(idx >> 2) * SPAD + MK + (idx & 3)] = 0.f;
        }
    }
    // preload norms (L2-hot)
    {
        const float* dbase = g_d + b * DIM;
        if (tid < TT) di_s[tid] = dbase[i0 + tid];
        else dj_s[tid - TT] = dbase[j0 + (tid - TT)];
    }
    const float* Bp = diag ? A : B;
    __syncthreads();

    // warp layout: 2(m) x 4(n); warp tile 64 rows x 32 cols
    int wid = tid >> 5, lane = tid & 31;
    int wm = wid & 1, wn = wid >> 1;
    int gid = lane >> 2, tig = lane & 3;
    int t2 = 2 * tig;

    float acc[4][4][4];
#pragma unroll
    for (int mt = 0; mt < 4; mt++)
#pragma unroll
        for (int nt = 0; nt < 4; nt++)
#pragma unroll
            for (int q = 0; q < 4; q++) acc[mt][nt][q] = 0.f;

    const float* arow = A + (wm * 64 + gid) * SPAD;
    const float* brow = Bp + (wn * 32 + gid) * SPAD;

    // ---- 6 fp16 k16-steps: k = 0..95 ----
    for (int ks = 0; ks < 6; ks++) {
        int k0 = ks * 16;
        // B frags: per nt, b[0] = k(2t,2t+1), b[1] = k(8+2t,9+2t) of col gid
        uint32_t bh[4][2], bl[4][2];
#pragma unroll
        for (int nt = 0; nt < 4; nt++) {
            const float* bp = brow + nt * 8 * SPAD + k0;
            split_h2(*(const float2*)(bp + t2),     bh[nt][0], bl[nt][0]);
            split_h2(*(const float2*)(bp + 8 + t2), bh[nt][1], bl[nt][1]);
        }
#pragma unroll
        for (int mt = 0; mt < 4; mt++) {
            const float* ap = arow + mt * 16 * SPAD + k0;
            uint32_t ah[4], al[4];
            split_h2(*(const float2*)(ap + t2),                ah[0], al[0]);  // row gid,  k 0..7 part
            split_h2(*(const float2*)(ap + 8 * SPAD + t2),     ah[1], al[1]);  // row gid+8
            split_h2(*(const float2*)(ap + 8 + t2),            ah[2], al[2]);  // row gid,  k 8..15 part
            split_h2(*(const float2*)(ap + 8 * SPAD + 8 + t2), ah[3], al[3]);  // row gid+8
#pragma unroll
            for (int nt = 0; nt < 4; nt++) {
                mma16(acc[mt][nt], ah, bh[nt]);
                mma16(acc[mt][nt], ah, bl[nt]);
                mma16(acc[mt][nt], al, bh[nt]);
            }
        }
    }

    // ---- 1 tf32 k8-step: k = 96..103 (zeros beyond 100) ----
    {
        const int k0 = 96;
        uint32_t bhi[4][2], blo[4][2];
#pragma unroll
        for (int nt = 0; nt < 4; nt++) {
            const float* bp = brow + nt * 8 * SPAD + k0 + tig;
            float r0 = bp[0], r1 = bp[4];
            bhi[nt][0] = f2tf32(r0);
            bhi[nt][1] = f2tf32(r1);
            blo[nt][0] = __float_as_uint(r0 - __uint_as_float(bhi[nt][0]));
            blo[nt][1] = __float_as_uint(r1 - __uint_as_float(bhi[nt][1]));
        }
#pragma unroll
        for (int mt = 0; mt < 4; mt++) {
            const float* ap = arow + mt * 16 * SPAD + k0 + tig;
            float r0 = ap[0];
            float r1 = ap[8 * SPAD];
            float r2 = ap[4];
            float r3 = ap[8 * SPAD + 4];
            uint32_t ahi[4], alo[4];
            ahi[0] = f2tf32(r0); alo[0] = __float_as_uint(r0 - __uint_as_float(ahi[0]));
            ahi[1] = f2tf32(r1); alo[1] = __float_as_uint(r1 - __uint_as_float(ahi[1]));
            ahi[2] = f2tf32(r2); alo[2] = __float_as_uint(r2 - __uint_as_float(ahi[2]));
            ahi[3] = f2tf32(r3); alo[3] = __float_as_uint(r3 - __uint_as_float(ahi[3]));
#pragma unroll
            for (int nt = 0; nt < 4; nt++) {
                mma8(acc[mt][nt], ahi, bhi[nt]);
                mma8(acc[mt][nt], ahi, blo[nt]);
                mma8(acc[mt][nt], alo, bhi[nt]);
            }
        }
    }

    __syncthreads();

    // ---- epilogue: transform + sums + triu-direct store ----
    float et = expf(t[0]);
    float* ob = out + (size_t)b * TRI;

#pragma unroll
    for (int mt = 0; mt < 4; mt++) {
        int rb = wm * 64 + mt * 16;
        int iA = i0 + rb + gid, iB = iA + 8;
        size_t offA = (size_t)iA * DIM - ((size_t)iA * (iA - 1)) / 2 - iA;
        size_t offB = (size_t)iB * DIM - ((size_t)iB * (iB - 1)) / 2 - iB;
        float diA = di_s[rb + gid];
        float diB = di_s[rb + gid + 8];
        float rsumA = 0.f, rsumB = 0.f;
#pragma unroll
        for (int nt = 0; nt < 4; nt++) {
            int cb = wn * 32 + nt * 8 + tig * 2;
            int jg = j0 + cb;
            float dj0 = dj_s[cb], dj1 = dj_s[cb + 1];
            float* c = acc[mt][nt];

            float q0 = fmaxf(fmaf(-2.f, c[0], diA + dj0), 0.f);
            float q1 = fmaxf(fmaf(-2.f, c[1], diA + dj1), 0.f);
            float q2 = fmaxf(fmaf(-2.f, c[2], diB + dj0), 0.f);
            float q3 = fmaxf(fmaf(-2.f, c[3], diB + dj1), 0.f);
            float v0 = sqrtf(fmaf(et, q0, EPSV));
            float v1 = sqrtf(fmaf(et, q1, EPSV));
            float v2 = sqrtf(fmaf(et, q2, EPSV));
            float v3 = sqrtf(fmaf(et, q3, EPSV));

            rsumA += v0 + v1;
            rsumB += v2 + v3;

            float cs0 = v0 + v2, cs1 = v1 + v3;
#pragma unroll
            for (int o = 4; o <= 16; o <<= 1) {
                cs0 += __shfl_xor_sync(0xffffffffu, cs0, o);
                cs1 += __shfl_xor_sync(0xffffffffu, cs1, o);
            }
            if (gid == 0) {
                atomicAdd(&cs_s[cb], cs0);
                atomicAdd(&cs_s[cb + 1], cs1);
            }

            if (!diag || jg >= iA)     ob[offA + jg]     = v0;
            if (!diag || jg + 1 >= iA) ob[offA + jg + 1] = v1;
            if (!diag || jg >= iB)     ob[offB + jg]     = v2;
            if (!diag || jg + 1 >= iB) ob[offB + jg + 1] = v3;
        }
#pragma unroll
        for (int o = 1; o <= 2; o <<= 1) {
            rsumA += __shfl_xor_sync(0xffffffffu, rsumA, o);
            rsumB += __shfl_xor_sync(0xffffffffu, rsumB, o);
        }
        if (tig == 0) {
            atomicAdd(&rs_s[rb + gid], rsumA);
            atomicAdd(&rs_s[rb + gid + 8], rsumB);
        }
    }
    __syncthreads();

    if (tid < TT) {
        g_sp[tj][b][i0 + tid] = rs_s[tid];
    } else if (!diag) {
        g_sp[ti][b][j0 + (tid - TT)] = cs_s[tid - TT];
    }
}

// ---------------------------------------------------------------------------
// Sums: per-batch row-sum vector (pre-scaled by 1/dim) + grand mean
// ---------------------------------------------------------------------------
__global__ __launch_bounds__(256)
void sums_kernel() {
    int b = blockIdx.x, tid = threadIdx.x;
    __shared__ float red[256];
    float part = 0.f;
    for (int i = tid; i < DIM; i += 256) {
        float v = g_sp[0][b][i] + g_sp[1][b][i] + g_sp[2][b][i]
                + g_sp[3][b][i] + g_sp[4][b][i];
        g_sb[b * DIM + i] = v * (1.0f / (float)DIM);
        part += v;
    }
    red[tid] = part;
    __syncthreads();
    for (int o = 128; o > 0; o >>= 1) {
        if (tid < o) red[tid] += red[tid + o];
        __syncthreads();
    }
    if (tid == 0) g_gm[b] = red[0] * (1.0f / ((float)DIM * (float)DIM));
}

// ---------------------------------------------------------------------------
// Center apply: in-place streaming RMW of out, one block per (row, batch)
// ---------------------------------------------------------------------------
__global__ __launch_bounds__(128)
void center_apply_kernel(float* __restrict__ out) {
    int i = blockIdx.x, b = blockIdx.y;
    const float* sb = g_sb + b * DIM;
    float corr = g_gm[b] - sb[i];
    float* ob = out + (size_t)b * TRI + ((size_t)i * DIM - ((size_t)i * (i - 1)) / 2);
    int L = DIM - i;
    int tid = threadIdx.x;

    int mis = (int)(((uintptr_t)ob >> 2) & 3);
    int head = (4 - mis) & 3;
    if (head > L) head = L;
    if (tid < head) ob[tid] = ob[tid] - sb[i + tid] + corr;

    int body = (L - head) >> 2;
    float4* vb = (float4*)(ob + head);
    for (int q = tid; q < body; q += 128) {
        float4 v = vb[q];
        int j = i + head + q * 4;
        v.x = v.x - sb[j]     + corr;
        v.y = v.y - sb[j + 1] + corr;
        v.z = v.z - sb[j + 2] + corr;
        v.w = v.w - sb[j + 3] + corr;
        vb[q] = v;
    }
    int done = head + body * 4;
    int tail = L - done;
    if (tid < tail) ob[done + tid] = ob[done + tid] - sb[i + done + tid] + corr;
}

// ---------------------------------------------------------------------------
extern "C" void kernel_launch(void* const* d_in, const int* in_sizes, int n_in,
                              void* d_out, int out_size) {
    const float* x = (const float*)d_in[0];
    const float* t = (const float*)d_in[1];
    float* out = (float*)d_out;

    const int smem1 = 2 * TSZ * (int)sizeof(float);  // 106496 B -> 2 CTAs/SM
    cudaFuncSetAttribute(gram_dcov_kernel,
                         cudaFuncAttributeMaxDynamicSharedMemorySize, smem1);

    int c1 = NROWS / 3, c2 = NROWS / 3;
    int c3 = NROWS - c1 - c2;
    norm_kernel<<<(c1 * 32 + 255) / 256, 256>>>(x, 0, c1);
    norm_kernel<<<(c2 * 32 + 255) / 256, 256>>>(x, c1, c2);
    norm_kernel<<<(c3 * 32 + 255) / 256, 256>>>(x, c1 + c2, c3);
    gram_dcov_kernel<<<dim3(NPAIR, BB), 256, smem1>>>(x, t, out);
    sums_kernel<<<BB, 256>>>();
    center_apply_kernel<<<dim3(DIM, BB), 128>>>(out);
}

// round 15
// speedup vs baseline: 1.4883x; 1.4883x over previous
#include <cuda_runtime.h>
#include <cuda_fp16.h>
#include <math.h>
#include <cstdint>

#define BB 64
#define DIM 640
#define MK 100
#define TT 128
#define NT 5            // DIM / TT
#define NPAIR 15        // upper tile pairs
#define TRI 205120      // 640*641/2
#define EPSV 1e-5f
#define SPADW 52        // words (half2) per row = 104 halfs
#define TSZW (TT * SPADW)
#define NROWS (BB * DIM)

// ---- scratch (static device arrays: allocation-free) ----
__device__ float g_sp[NT][BB][DIM];   // row-sum slots (exactly-once writes)
__device__ float g_d[NROWS];          // squared norms
__device__ float g_sb[NROWS];         // per-batch row sums, pre-scaled by 1/dim
__device__ float g_gm[BB];            // per-batch grand mean

// ---------------------------------------------------------------------------
// fp16 m16n8k16 MMA, f32 accumulate
__device__ __forceinline__ void mma16(float* c, const uint32_t* a, const uint32_t* b) {
    asm volatile(
        "mma.sync.aligned.m16n8k16.row.col.f32.f16.f16.f32 "
        "{%0,%1,%2,%3}, {%4,%5,%6,%7}, {%8,%9}, {%0,%1,%2,%3};"
        : "+f"(c[0]), "+f"(c[1]), "+f"(c[2]), "+f"(c[3])
        : "r"(a[0]), "r"(a[1]), "r"(a[2]), "r"(a[3]), "r"(b[0]), "r"(b[1]));
}
// fp16 m16n8k8 MMA (tail k-step)
__device__ __forceinline__ void mma8h(float* c, uint32_t a0, uint32_t a1, uint32_t b0) {
    asm volatile(
        "mma.sync.aligned.m16n8k8.row.col.f32.f16.f16.f32 "
        "{%0,%1,%2,%3}, {%4,%5}, {%6}, {%0,%1,%2,%3};"
        : "+f"(c[0]), "+f"(c[1]), "+f"(c[2]), "+f"(c[3])
        : "r"(a0), "r"(a1), "r"(b0));
}

// ---------------------------------------------------------------------------
// Norms: one warp per x-row (coalesced), split over batch thirds
// ---------------------------------------------------------------------------
__global__ void norm_kernel(const float* __restrict__ x, int row0, int nrows) {
    int w = (blockIdx.x * 256 + threadIdx.x) >> 5;
    int lane = threadIdx.x & 31;
    if (w >= nrows) return;
    const float* xr = x + (size_t)(row0 + w) * MK;
    float s = 0.f;
#pragma unroll
    for (int k = lane; k < MK; k += 32) { float v = xr[k]; s = fmaf(v, v, s); }
#pragma unroll
    for (int o = 16; o >= 1; o >>= 1) s += __shfl_xor_sync(0xffffffffu, s, o);
    if (lane == 0) g_d[row0 + w] = s;
}

// ---------------------------------------------------------------------------
// Gram: smem-pre-split fp16 hi/lo tiles, pure LDS.64 + HMMA mainloop.
// 256 threads, 64x32 warp tiles, 2 CTAs/SM, triu-direct store.
// ---------------------------------------------------------------------------
__global__ __launch_bounds__(256, 2)
void gram_dcov_kernel(const float* __restrict__ x, const float* __restrict__ t,
                      float* __restrict__ out) {
    int p = blockIdx.x, b = blockIdx.y;
    int ti = 0, rem = p;
    while (rem >= NT - ti) { rem -= NT - ti; ti++; }
    int tj = ti + rem;
    int i0 = ti * TT, j0 = tj * TT;
    bool diag = (ti == tj);

    extern __shared__ uint32_t smw[];
    uint32_t* AhiW = smw;                // each tile: TT*SPADW words (half2)
    uint32_t* AloW = AhiW + TSZW;
    uint32_t* BhiW = AloW + TSZW;
    uint32_t* BloW = BhiW + TSZW;

    __shared__ float di_s[TT], dj_s[TT], rs_s[TT], cs_s[TT];

    int tid = threadIdx.x;
    if (tid < TT) { rs_s[tid] = 0.f; cs_s[tid] = 0.f; }

    const float* xb = x + (size_t)b * DIM * MK;

    // ---- stage: fp32 -> fp16 (hi, lo) pairs, permuted-k16 layout ----
    // word layout per row: k-blocks of 16 at words [bk*8 .. bk*8+7], halfs
    // ordered [0,1,8,9, 2,3,10,11, 4,5,12,13, 6,7,14,15]; k 96..103 straight.
    {
        const float* srcA = xb + (size_t)i0 * MK;
        const float* srcB = xb + (size_t)j0 * MK;
        int nmat = diag ? 1 : 2;
        for (int mat = 0; mat < nmat; mat++) {
            const float* src = mat ? srcB : srcA;
            uint32_t* dh = mat ? BhiW : AhiW;
            uint32_t* dl = mat ? BloW : AloW;
            for (int idx = tid; idx < TSZW; idx += 256) {
                int r = idx / SPADW, m = idx - r * SPADW;  // m = k-pair index
                int k = 2 * m;
                float2 v;
                if (k < MK) v = *(const float2*)(src + r * MK + k);
                else v = make_float2(0.f, 0.f);
                __half2 h = __floats2half2_rn(v.x, v.y);
                __half2 l = __floats2half2_rn(v.x - __low2float(h),
                                              v.y - __high2float(h));
                int mm = m & 7;
                int wofs = (m < 48) ? ((m >> 3) * 8 + 2 * (mm & 3) + (mm >> 2)) : m;
                int d = r * SPADW + wofs;
                dh[d] = *reinterpret_cast<uint32_t*>(&h);
                dl[d] = *reinterpret_cast<uint32_t*>(&l);
            }
        }
    }
    // preload norms (L2-hot)
    {
        const float* dbase = g_d + b * DIM;
        if (tid < TT) di_s[tid] = dbase[i0 + tid];
        else dj_s[tid - TT] = dbase[j0 + (tid - TT)];
    }
    const uint32_t* BhP = diag ? AhiW : BhiW;
    const uint32_t* BlP = diag ? AloW : BloW;
    __syncthreads();

    // warp layout: 2(m) x 4(n); warp tile 64 rows x 32 cols
    int wid = tid >> 5, lane = tid & 31;
    int wm = wid & 1, wn = wid >> 1;
    int gid = lane >> 2, tig = lane & 3;

    float acc[4][4][4];
#pragma unroll
    for (int mt = 0; mt < 4; mt++)
#pragma unroll
        for (int nt = 0; nt < 4; nt++)
#pragma unroll
            for (int q = 0; q < 4; q++) acc[mt][nt][q] = 0.f;

    const uint32_t* ah0 = AhiW + (wm * 64 + gid) * SPADW + 2 * tig;
    const uint32_t* al0 = AloW + (wm * 64 + gid) * SPADW + 2 * tig;
    const uint32_t* bh0 = BhP + (wn * 32 + gid) * SPADW + 2 * tig;
    const uint32_t* bl0 = BlP + (wn * 32 + gid) * SPADW + 2 * tig;

    // ---- 6 fp16 k16-steps (k 0..95): pure LDS.64 + HMMA ----
    for (int ks = 0; ks < 6; ks++) {
        int k0 = ks * 8;  // word offset
        uint32_t bh[4][2], bl[4][2];
#pragma unroll
        for (int nt = 0; nt < 4; nt++) {
            uint2 h = *(const uint2*)(bh0 + nt * 8 * SPADW + k0);
            uint2 l = *(const uint2*)(bl0 + nt * 8 * SPADW + k0);
            bh[nt][0] = h.x; bh[nt][1] = h.y;
            bl[nt][0] = l.x; bl[nt][1] = l.y;
        }
#pragma unroll
        for (int mt = 0; mt < 4; mt++) {
            uint2 hl = *(const uint2*)(ah0 + (mt * 16) * SPADW + k0);
            uint2 hh = *(const uint2*)(ah0 + (mt * 16 + 8) * SPADW + k0);
            uint2 ll = *(const uint2*)(al0 + (mt * 16) * SPADW + k0);
            uint2 lh = *(const uint2*)(al0 + (mt * 16 + 8) * SPADW + k0);
            uint32_t ah[4] = {hl.x, hh.x, hl.y, hh.y};
            uint32_t al[4] = {ll.x, lh.x, ll.y, lh.y};
#pragma unroll
            for (int nt = 0; nt < 4; nt++) {
                mma16(acc[mt][nt], ah, bh[nt]);
                mma16(acc[mt][nt], ah, bl[nt]);
                mma16(acc[mt][nt], al, bh[nt]);
            }
        }
    }
    // ---- fp16 k8 tail (k 96..103, stored straight at words 48..51) ----
    {
        const int k0 = 48;  // word offset; thread word = k0 + tig
        uint32_t bh[4], bl[4];
#pragma unroll
        for (int nt = 0; nt < 4; nt++) {
            bh[nt] = *(bh0 - 2 * tig + nt * 8 * SPADW + k0 + tig);
            bl[nt] = *(bl0 - 2 * tig + nt * 8 * SPADW + k0 + tig);
        }
#pragma unroll
        for (int mt = 0; mt < 4; mt++) {
            uint32_t ahl = *(ah0 - 2 * tig + (mt * 16) * SPADW + k0 + tig);
            uint32_t ahh = *(ah0 - 2 * tig + (mt * 16 + 8) * SPADW + k0 + tig);
            uint32_t all = *(al0 - 2 * tig + (mt * 16) * SPADW + k0 + tig);
            uint32_t alh = *(al0 - 2 * tig + (mt * 16 + 8) * SPADW + k0 + tig);
#pragma unroll
            for (int nt = 0; nt < 4; nt++) {
                mma8h(acc[mt][nt], ahl, ahh, bh[nt]);
                mma8h(acc[mt][nt], ahl, ahh, bl[nt]);
                mma8h(acc[mt][nt], all, alh, bh[nt]);
            }
        }
    }

    __syncthreads();

    // ---- epilogue: transform + sums + triu-direct store ----
    float et = expf(t[0]);
    float* ob = out + (size_t)b * TRI;

#pragma unroll
    for (int mt = 0; mt < 4; mt++) {
        int rb = wm * 64 + mt * 16;
        int iA = i0 + rb + gid, iB = iA + 8;
        size_t offA = (size_t)iA * DIM - ((size_t)iA * (iA - 1)) / 2 - iA;
        size_t offB = (size_t)iB * DIM - ((size_t)iB * (iB - 1)) / 2 - iB;
        float diA = di_s[rb + gid];
        float diB = di_s[rb + gid + 8];
        float rsumA = 0.f, rsumB = 0.f;
#pragma unroll
        for (int nt = 0; nt < 4; nt++) {
            int cb = wn * 32 + nt * 8 + tig * 2;
            int jg = j0 + cb;
            float dj0 = dj_s[cb], dj1 = dj_s[cb + 1];
            float* c = acc[mt][nt];

            float q0 = fmaxf(fmaf(-2.f, c[0], diA + dj0), 0.f);
            float q1 = fmaxf(fmaf(-2.f, c[1], diA + dj1), 0.f);
            float q2 = fmaxf(fmaf(-2.f, c[2], diB + dj0), 0.f);
            float q3 = fmaxf(fmaf(-2.f, c[3], diB + dj1), 0.f);
            float v0 = sqrtf(fmaf(et, q0, EPSV));
            float v1 = sqrtf(fmaf(et, q1, EPSV));
            float v2 = sqrtf(fmaf(et, q2, EPSV));
            float v3 = sqrtf(fmaf(et, q3, EPSV));

            rsumA += v0 + v1;
            rsumB += v2 + v3;

            float cs0 = v0 + v2, cs1 = v1 + v3;
#pragma unroll
            for (int o = 4; o <= 16; o <<= 1) {
                cs0 += __shfl_xor_sync(0xffffffffu, cs0, o);
                cs1 += __shfl_xor_sync(0xffffffffu, cs1, o);
            }
            if (gid == 0) {
                atomicAdd(&cs_s[cb], cs0);
                atomicAdd(&cs_s[cb + 1], cs1);
            }

            if (!diag || jg >= iA)     ob[offA + jg]     = v0;
            if (!diag || jg + 1 >= iA) ob[offA + jg + 1] = v1;
            if (!diag || jg >= iB)     ob[offB + jg]     = v2;
            if (!diag || jg + 1 >= iB) ob[offB + jg + 1] = v3;
        }
#pragma unroll
        for (int o = 1; o <= 2; o <<= 1) {
            rsumA += __shfl_xor_sync(0xffffffffu, rsumA, o);
            rsumB += __shfl_xor_sync(0xffffffffu, rsumB, o);
        }
        if (tig == 0) {
            atomicAdd(&rs_s[rb + gid], rsumA);
            atomicAdd(&rs_s[rb + gid + 8], rsumB);
        }
    }
    __syncthreads();

    if (tid < TT) {
        g_sp[tj][b][i0 + tid] = rs_s[tid];
    } else if (!diag) {
        g_sp[ti][b][j0 + (tid - TT)] = cs_s[tid - TT];
    }
}

// ---------------------------------------------------------------------------
// Sums: per-batch row-sum vector (pre-scaled by 1/dim) + grand mean
// ---------------------------------------------------------------------------
__global__ __launch_bounds__(256)
void sums_kernel() {
    int b = blockIdx.x, tid = threadIdx.x;
    __shared__ float red[256];
    float part = 0.f;
    for (int i = tid; i < DIM; i += 256) {
        float v = g_sp[0][b][i] + g_sp[1][b][i] + g_sp[2][b][i]
                + g_sp[3][b][i] + g_sp[4][b][i];
        g_sb[b * DIM + i] = v * (1.0f / (float)DIM);
        part += v;
    }
    red[tid] = part;
    __syncthreads();
    for (int o = 128; o > 0; o >>= 1) {
        if (tid < o) red[tid] += red[tid + o];
        __syncthreads();
    }
    if (tid == 0) g_gm[b] = red[0] * (1.0f / ((float)DIM * (float)DIM));
}

// ---------------------------------------------------------------------------
// Center apply: in-place streaming RMW of out, one block per (row, batch)
// ---------------------------------------------------------------------------
__global__ __launch_bounds__(128)
void center_apply_kernel(float* __restrict__ out) {
    int i = blockIdx.x, b = blockIdx.y;
    const float* sb = g_sb + b * DIM;
    float corr = g_gm[b] - sb[i];
    float* ob = out + (size_t)b * TRI + ((size_t)i * DIM - ((size_t)i * (i - 1)) / 2);
    int L = DIM - i;
    int tid = threadIdx.x;

    int mis = (int)(((uintptr_t)ob >> 2) & 3);
    int head = (4 - mis) & 3;
    if (head > L) head = L;
    if (tid < head) ob[tid] = ob[tid] - sb[i + tid] + corr;

    int body = (L - head) >> 2;
    float4* vb = (float4*)(ob + head);
    for (int q = tid; q < body; q += 128) {
        float4 v = vb[q];
        int j = i + head + q * 4;
        v.x = v.x - sb[j]     + corr;
        v.y = v.y - sb[j + 1] + corr;
        v.z = v.z - sb[j + 2] + corr;
        v.w = v.w - sb[j + 3] + corr;
        vb[q] = v;
    }
    int done = head + body * 4;
    int tail = L - done;
    if (tid < tail) ob[done + tid] = ob[done + tid] - sb[i + done + tid] + corr;
}

// ---------------------------------------------------------------------------
extern "C" void kernel_launch(void* const* d_in, const int* in_sizes, int n_in,
                              void* d_out, int out_size) {
    const float* x = (const float*)d_in[0];
    const float* t = (const float*)d_in[1];
    float* out = (float*)d_out;

    const int smem1 = 4 * TSZW * (int)sizeof(uint32_t);  // 106496 B -> 2 CTAs/SM
    cudaFuncSetAttribute(gram_dcov_kernel,
                         cudaFuncAttributeMaxDynamicSharedMemorySize, smem1);

    int c1 = NROWS / 3, c2 = NROWS / 3;
    int c3 = NROWS - c1 - c2;
    norm_kernel<<<(c1 * 32 + 255) / 256, 256>>>(x, 0, c1);
    norm_kernel<<<(c2 * 32 + 255) / 256, 256>>>(x, c1, c2);
    norm_kernel<<<(c3 * 32 + 255) / 256, 256>>>(x, c1 + c2, c3);
    gram_dcov_kernel<<<dim3(NPAIR, BB), 256, smem1>>>(x, t, out);
    sums_kernel<<<BB, 256>>>();
    center_apply_kernel<<<dim3(DIM, BB), 128>>>(out);
}

// round 16
// speedup vs baseline: 1.8047x; 1.2126x over previous
#include <cuda_runtime.h>
#include <cuda_fp16.h>
#include <math.h>
#include <cstdint>

#define BB 64
#define DIM 640
#define MK 100
#define TT 128
#define NT 5            // DIM / TT
#define NPAIR 15        // upper tile pairs
#define TRI 205120      // 640*641/2
#define EPSV 1e-5f
#define SPADW 52        // words (half2) per row = 104 halfs
#define TSZW (TT * SPADW)
#define NROWS (BB * DIM)

// ---- scratch (static device arrays: allocation-free) ----
__device__ float g_sp[NT][BB][DIM];   // row-sum slots (exactly-once writes)
__device__ float g_d[NROWS];          // squared norms
__device__ float g_sb[NROWS];         // per-batch row sums, pre-scaled by 1/dim
__device__ float g_gm[BB];            // per-batch grand mean

// ---------------------------------------------------------------------------
// fp16 m16n8k16 MMA, f32 accumulate
__device__ __forceinline__ void mma16(float* c, const uint32_t* a, const uint32_t* b) {
    asm volatile(
        "mma.sync.aligned.m16n8k16.row.col.f32.f16.f16.f32 "
        "{%0,%1,%2,%3}, {%4,%5,%6,%7}, {%8,%9}, {%0,%1,%2,%3};"
        : "+f"(c[0]), "+f"(c[1]), "+f"(c[2]), "+f"(c[3])
        : "r"(a[0]), "r"(a[1]), "r"(a[2]), "r"(a[3]), "r"(b[0]), "r"(b[1]));
}
// fp16 m16n8k8 MMA (tail k-step)
__device__ __forceinline__ void mma8h(float* c, uint32_t a0, uint32_t a1, uint32_t b0) {
    asm volatile(
        "mma.sync.aligned.m16n8k8.row.col.f32.f16.f16.f32 "
        "{%0,%1,%2,%3}, {%4,%5}, {%6}, {%0,%1,%2,%3};"
        : "+f"(c[0]), "+f"(c[1]), "+f"(c[2]), "+f"(c[3])
        : "r"(a0), "r"(a1), "r"(b0));
}

// ---------------------------------------------------------------------------
// Norms: one warp per x-row (coalesced), single launch
// ---------------------------------------------------------------------------
__global__ void norm_kernel(const float* __restrict__ x) {
    int w = (blockIdx.x * 256 + threadIdx.x) >> 5;
    int lane = threadIdx.x & 31;
    if (w >= NROWS) return;
    const float* xr = x + (size_t)w * MK;
    float s = 0.f;
#pragma unroll
    for (int k = lane; k < MK; k += 32) { float v = xr[k]; s = fmaf(v, v, s); }
#pragma unroll
    for (int o = 16; o >= 1; o >>= 1) s += __shfl_xor_sync(0xffffffffu, s, o);
    if (lane == 0) g_d[w] = s;
}

// ---------------------------------------------------------------------------
// Gram: smem-pre-split fp16 hi/lo tiles, pure LDS.64 + HMMA mainloop.
// 256 threads, 64x32 warp tiles, 2 CTAs/SM, triu-direct store.
// ---------------------------------------------------------------------------
__global__ __launch_bounds__(256, 2)
void gram_dcov_kernel(const float* __restrict__ x, const float* __restrict__ t,
                      float* __restrict__ out) {
    int p = blockIdx.x, b = blockIdx.y;
    int ti = 0, rem = p;
    while (rem >= NT - ti) { rem -= NT - ti; ti++; }
    int tj = ti + rem;
    int i0 = ti * TT, j0 = tj * TT;
    bool diag = (ti == tj);

    extern __shared__ uint32_t smw[];
    uint32_t* AhiW = smw;                // each tile: TT*SPADW words (half2)
    uint32_t* AloW = AhiW + TSZW;
    uint32_t* BhiW = AloW + TSZW;
    uint32_t* BloW = BhiW + TSZW;

    __shared__ float di_s[TT], dj_s[TT], rs_s[TT], cs_s[TT];

    int tid = threadIdx.x;
    if (tid < TT) { rs_s[tid] = 0.f; cs_s[tid] = 0.f; }

    const float* xb = x + (size_t)b * DIM * MK;

    // ---- stage: fp32 -> fp16 (hi, lo), permuted-k16 layout, shift-only math ----
    // per row: k-blocks of 16 at words [bk*8..bk*8+7], halfs ordered
    // [0,1,8,9, 2,3,10,11, 4,5,12,13, 6,7,14,15]; k 96..103 straight at words 48..51.
    {
        const float* srcA = xb + (size_t)i0 * MK;
        const float* srcB = xb + (size_t)j0 * MK;
        int nmat = diag ? 1 : 2;
        for (int mat = 0; mat < nmat; mat++) {
            const float* src = mat ? srcB : srcA;
            uint32_t* dh = mat ? BhiW : AhiW;
            uint32_t* dl = mat ? BloW : AloW;
#pragma unroll
            for (int it = 0; it < 32; it++) {
                int idx = tid + it * 256;          // domain TT*64
                int r = idx >> 6, m = idx & 63;    // m = k-pair index
                if (m >= SPADW) continue;
                int k = m << 1;
                float2 v;
                if (k < MK) v = *(const float2*)(src + r * MK + k);
                else v = make_float2(0.f, 0.f);
                __half2 h = __floats2half2_rn(v.x, v.y);
                __half2 l = __floats2half2_rn(v.x - __low2float(h),
                                              v.y - __high2float(h));
                int mm = m & 7;
                int wofs = (m < 48) ? ((m & ~7) + ((mm & 3) << 1) + (mm >> 2)) : m;
                int d = r * SPADW + wofs;
                dh[d] = *reinterpret_cast<uint32_t*>(&h);
                dl[d] = *reinterpret_cast<uint32_t*>(&l);
            }
        }
    }
    // preload norms (L2-hot)
    {
        const float* dbase = g_d + b * DIM;
        if (tid < TT) di_s[tid] = dbase[i0 + tid];
        else dj_s[tid - TT] = dbase[j0 + (tid - TT)];
    }
    const uint32_t* BhP = diag ? AhiW : BhiW;
    const uint32_t* BlP = diag ? AloW : BloW;
    __syncthreads();

    // warp layout: 2(m) x 4(n); warp tile 64 rows x 32 cols
    int wid = tid >> 5, lane = tid & 31;
    int wm = wid & 1, wn = wid >> 1;
    int gid = lane >> 2, tig = lane & 3;

    float acc[4][4][4];
#pragma unroll
    for (int mt = 0; mt < 4; mt++)
#pragma unroll
        for (int nt = 0; nt < 4; nt++)
#pragma unroll
            for (int q = 0; q < 4; q++) acc[mt][nt][q] = 0.f;

    const uint32_t* ah0 = AhiW + (wm * 64 + gid) * SPADW + 2 * tig;
    const uint32_t* al0 = AloW + (wm * 64 + gid) * SPADW + 2 * tig;
    const uint32_t* bh0 = BhP + (wn * 32 + gid) * SPADW + 2 * tig;
    const uint32_t* bl0 = BlP + (wn * 32 + gid) * SPADW + 2 * tig;

    // ---- 6 fp16 k16-steps (k 0..95): pure LDS.64 + HMMA, fully unrolled ----
#pragma unroll
    for (int ks = 0; ks < 6; ks++) {
        int k0 = ks * 8;  // word offset
        uint32_t bh[4][2], bl[4][2];
#pragma unroll
        for (int nt = 0; nt < 4; nt++) {
            uint2 h = *(const uint2*)(bh0 + nt * 8 * SPADW + k0);
            uint2 l = *(const uint2*)(bl0 + nt * 8 * SPADW + k0);
            bh[nt][0] = h.x; bh[nt][1] = h.y;
            bl[nt][0] = l.x; bl[nt][1] = l.y;
        }
#pragma unroll
        for (int mt = 0; mt < 4; mt++) {
            uint2 hl = *(const uint2*)(ah0 + (mt * 16) * SPADW + k0);
            uint2 hh = *(const uint2*)(ah0 + (mt * 16 + 8) * SPADW + k0);
            uint2 ll = *(const uint2*)(al0 + (mt * 16) * SPADW + k0);
            uint2 lh = *(const uint2*)(al0 + (mt * 16 + 8) * SPADW + k0);
            uint32_t ah[4] = {hl.x, hh.x, hl.y, hh.y};
            uint32_t al[4] = {ll.x, lh.x, ll.y, lh.y};
#pragma unroll
            for (int nt = 0; nt < 4; nt++) {
                mma16(acc[mt][nt], ah, bh[nt]);
                mma16(acc[mt][nt], ah, bl[nt]);
                mma16(acc[mt][nt], al, bh[nt]);
            }
        }
    }
    // ---- fp16 k8 tail (k 96..103, stored straight at words 48..51) ----
    {
        const int k0 = 48;  // word offset; thread word = k0 + tig
        uint32_t bh[4], bl[4];
#pragma unroll
        for (int nt = 0; nt < 4; nt++) {
            bh[nt] = *(bh0 - 2 * tig + nt * 8 * SPADW + k0 + tig);
            bl[nt] = *(bl0 - 2 * tig + nt * 8 * SPADW + k0 + tig);
        }
#pragma unroll
        for (int mt = 0; mt < 4; mt++) {
            uint32_t ahl = *(ah0 - 2 * tig + (mt * 16) * SPADW + k0 + tig);
            uint32_t ahh = *(ah0 - 2 * tig + (mt * 16 + 8) * SPADW + k0 + tig);
            uint32_t all = *(al0 - 2 * tig + (mt * 16) * SPADW + k0 + tig);
            uint32_t alh = *(al0 - 2 * tig + (mt * 16 + 8) * SPADW + k0 + tig);
#pragma unroll
            for (int nt = 0; nt < 4; nt++) {
                mma8h(acc[mt][nt], ahl, ahh, bh[nt]);
                mma8h(acc[mt][nt], ahl, ahh, bl[nt]);
                mma8h(acc[mt][nt], all, alh, bh[nt]);
            }
        }
    }

    __syncthreads();

    // ---- epilogue: transform + sums + triu-direct store (int32 offsets) ----
    float et = expf(t[0]);
    float* ob = out + (size_t)b * TRI;

    float csA[4] = {0.f, 0.f, 0.f, 0.f};   // col partials (even col of pair)
    float csB[4] = {0.f, 0.f, 0.f, 0.f};   // col partials (odd col of pair)

#pragma unroll
    for (int mt = 0; mt < 4; mt++) {
        int rb = wm * 64 + mt * 16;
        int iA = i0 + rb + gid, iB = iA + 8;
        int offA = iA * DIM - (iA * (iA - 1)) / 2 - iA;
        int offB = iB * DIM - (iB * (iB - 1)) / 2 - iB;
        float diA = di_s[rb + gid];
        float diB = di_s[rb + gid + 8];
        float rsumA = 0.f, rsumB = 0.f;
#pragma unroll
        for (int nt = 0; nt < 4; nt++) {
            int cb = wn * 32 + nt * 8 + tig * 2;
            int jg = j0 + cb;
            float dj0 = dj_s[cb], dj1 = dj_s[cb + 1];
            float* c = acc[mt][nt];

            float q0 = fmaxf(fmaf(-2.f, c[0], diA + dj0), 0.f);
            float q1 = fmaxf(fmaf(-2.f, c[1], diA + dj1), 0.f);
            float q2 = fmaxf(fmaf(-2.f, c[2], diB + dj0), 0.f);
            float q3 = fmaxf(fmaf(-2.f, c[3], diB + dj1), 0.f);
            float v0 = sqrtf(fmaf(et, q0, EPSV));
            float v1 = sqrtf(fmaf(et, q1, EPSV));
            float v2 = sqrtf(fmaf(et, q2, EPSV));
            float v3 = sqrtf(fmaf(et, q3, EPSV));

            rsumA += v0 + v1;
            rsumB += v2 + v3;
            csA[nt] += v0 + v2;
            csB[nt] += v1 + v3;

            if (!diag || jg >= iA)     ob[offA + jg]     = v0;
            if (!diag || jg + 1 >= iA) ob[offA + jg + 1] = v1;
            if (!diag || jg >= iB)     ob[offB + jg]     = v2;
            if (!diag || jg + 1 >= iB) ob[offB + jg + 1] = v3;
        }
#pragma unroll
        for (int o = 1; o <= 2; o <<= 1) {
            rsumA += __shfl_xor_sync(0xffffffffu, rsumA, o);
            rsumB += __shfl_xor_sync(0xffffffffu, rsumB, o);
        }
        if (tig == 0) {
            atomicAdd(&rs_s[rb + gid], rsumA);
            atomicAdd(&rs_s[rb + gid + 8], rsumB);
        }
    }
    // column-sum reduction once (off-diagonal tiles only)
    if (!diag) {
#pragma unroll
        for (int nt = 0; nt < 4; nt++) {
            float c0 = csA[nt], c1 = csB[nt];
#pragma unroll
            for (int o = 4; o <= 16; o <<= 1) {
                c0 += __shfl_xor_sync(0xffffffffu, c0, o);
                c1 += __shfl_xor_sync(0xffffffffu, c1, o);
            }
            if (gid == 0) {
                int cb = wn * 32 + nt * 8 + tig * 2;
                atomicAdd(&cs_s[cb], c0);
                atomicAdd(&cs_s[cb + 1], c1);
            }
        }
    }
    __syncthreads();

    if (tid < TT) {
        g_sp[tj][b][i0 + tid] = rs_s[tid];
    } else if (!diag) {
        g_sp[ti][b][j0 + (tid - TT)] = cs_s[tid - TT];
    }
}

// ---------------------------------------------------------------------------
// Sums: per-batch row-sum vector (pre-scaled by 1/dim) + grand mean
// ---------------------------------------------------------------------------
__global__ __launch_bounds__(256)
void sums_kernel() {
    int b = blockIdx.x, tid = threadIdx.x;
    __shared__ float red[256];
    float part = 0.f;
    for (int i = tid; i < DIM; i += 256) {
        float v = g_sp[0][b][i] + g_sp[1][b][i] + g_sp[2][b][i]
                + g_sp[3][b][i] + g_sp[4][b][i];
        g_sb[b * DIM + i] = v * (1.0f / (float)DIM);
        part += v;
    }
    red[tid] = part;
    __syncthreads();
    for (int o = 128; o > 0; o >>= 1) {
        if (tid < o) red[tid] += red[tid + o];
        __syncthreads();
    }
    if (tid == 0) g_gm[b] = red[0] * (1.0f / ((float)DIM * (float)DIM));
}

// ---------------------------------------------------------------------------
// Center apply: in-place streaming RMW of out, one block per (row, batch)
// ---------------------------------------------------------------------------
__global__ __launch_bounds__(128)
void center_apply_kernel(float* __restrict__ out) {
    int i = blockIdx.x, b = blockIdx.y;
    const float* sb = g_sb + b * DIM;
    float corr = g_gm[b] - sb[i];
    float* ob = out + (size_t)b * TRI + ((size_t)i * DIM - ((size_t)i * (i - 1)) / 2);
    int L = DIM - i;
    int tid = threadIdx.x;

    int mis = (int)(((uintptr_t)ob >> 2) & 3);
    int head = (4 - mis) & 3;
    if (head > L) head = L;
    if (tid < head) ob[tid] = ob[tid] - sb[i + tid] + corr;

    int body = (L - head) >> 2;
    float4* vb = (float4*)(ob + head);
    for (int q = tid; q < body; q += 128) {
        float4 v = vb[q];
        int j = i + head + q * 4;
        v.x = v.x - sb[j]     + corr;
        v.y = v.y - sb[j + 1] + corr;
        v.z = v.z - sb[j + 2] + corr;
        v.w = v.w - sb[j + 3] + corr;
        vb[q] = v;
    }
    int done = head + body * 4;
    int tail = L - done;
    if (tid < tail) ob[done + tid] = ob[done + tid] - sb[i + done + tid] + corr;
}

// ---------------------------------------------------------------------------
extern "C" void kernel_launch(void* const* d_in, const int* in_sizes, int n_in,
                              void* d_out, int out_size) {
    const float* x = (const float*)d_in[0];
    const float* t = (const float*)d_in[1];
    float* out = (float*)d_out;

    const int smem1 = 4 * TSZW * (int)sizeof(uint32_t);  // 106496 B -> 2 CTAs/SM
    cudaFuncSetAttribute(gram_dcov_kernel,
                         cudaFuncAttributeMaxDynamicSharedMemorySize, smem1);

    norm_kernel<<<(NROWS * 32 + 255) / 256, 256>>>(x);
    gram_dcov_kernel<<<dim3(NPAIR, BB), 256, smem1>>>(x, t, out);
    sums_kernel<<<BB, 256>>>();
    center_apply_kernel<<<dim3(DIM, BB), 128>>>(out);
}